// round 1
// baseline (speedup 1.0000x reference)
#include <cuda_runtime.h>

#define Bz 128
#define Sz 512
#define Hz 256
#define Ez 16
#define Vz 256
#define NCTA 128

// h sequence: slab 0 = h0 = zeros (never written), slabs 1..512 = h_t.
// Layout [t][j][b] so the recurrence reads coalesced over b.
__device__ float g_hseq[Sz + 1][Hz][Bz];   // ~67 MB, zero-init at module load
__device__ unsigned g_bar = 0;             // monotonic grid barrier counter
__device__ unsigned g_done = 0;            // end-of-kernel reset rendezvous

__device__ __forceinline__ float sigmf(float v) {
    return 1.0f / (1.0f + __expf(-v));
}

// ---------------------------------------------------------------------------
// Phase 1: persistent GRU recurrence. 128 CTAs (CTA c owns j = 2c, 2c+1),
// 256 threads: lower 128 threads do K in [0,128), upper do K in [128,256)
// plus the embedding-side gate preactivations (gi). Grid barrier each step.
// ---------------------------------------------------------------------------
__global__ void __launch_bounds__(256, 1)
gru_phase1(const int* __restrict__ x,
           const float* __restrict__ embed,
           const float* __restrict__ W_ih, const float* __restrict__ b_ih,
           const float* __restrict__ W_hh, const float* __restrict__ b_hh)
{
    __shared__ float w_s[Hz * 8];        // [k][jj*4 + g], g in {r,z,n}, 8 KB
    __shared__ float emb_s[Vz * 17];     // padded row 17 -> conflict-free gather
    __shared__ float wih_s[Ez * 8];      // [e][jj*4 + g]
    __shared__ float bias_s[16];         // [0..7] b_ih(jj,g), [8..15] b_hh(jj,g)
    __shared__ float red_s[128 * 12];    // 6 K-partials + 6 gi per lower slot

    const int tid = threadIdx.x;
    const int c   = blockIdx.x;
    const int j0  = 2 * c;

    // --- one-time loads ---
    for (int i = tid; i < Hz * 6; i += 256) {
        int k = i / 6, q = i - 6 * k;
        int g = q >> 1, jj = q & 1;
        w_s[k * 8 + jj * 4 + g] = W_hh[k * 768 + g * 256 + j0 + jj];
    }
    for (int i = tid; i < Vz * Ez; i += 256) {
        int v = i >> 4, e = i & 15;
        emb_s[v * 17 + e] = embed[i];
    }
    if (tid < Ez * 6) {
        int e = tid / 6, q = tid - 6 * e;
        int g = q >> 1, jj = q & 1;
        wih_s[e * 8 + jj * 4 + g] = W_ih[e * 768 + g * 256 + j0 + jj];
    }
    if (tid < 6) {
        int g = tid >> 1, jj = tid & 1;
        bias_s[jj * 4 + g]     = b_ih[g * 256 + j0 + jj];
        bias_s[8 + jj * 4 + g] = b_hh[g * 256 + j0 + jj];
    }
    __syncthreads();

    const int half = tid >> 7;        // 0 = lower (K 0..127 + gates), 1 = upper (K 128..255 + gi)
    const int lt   = tid & 127;
    const int jj   = lt >> 6;
    const int bb   = lt & 63;         // handles b = 2bb, 2bb+1
    const int j    = j0 + jj;
    const int kofs = half * 128;

    for (int t = 0; t < Sz; ++t) {
        const float* hrow = &g_hseq[t][0][0];

        // gi = b_ih + emb[x[b,t]] @ W_ih  (upper half only; overlaps K-loop issue)
        float gi_r0 = 0.f, gi_z0 = 0.f, gi_n0 = 0.f;
        float gi_r1 = 0.f, gi_z1 = 0.f, gi_n1 = 0.f;
        if (half) {
            int xv0 = __ldg(&x[(2 * bb)     * Sz + t]);
            int xv1 = __ldg(&x[(2 * bb + 1) * Sz + t]);
            gi_r0 = bias_s[jj * 4 + 0]; gi_z0 = bias_s[jj * 4 + 1]; gi_n0 = bias_s[jj * 4 + 2];
            gi_r1 = gi_r0; gi_z1 = gi_z0; gi_n1 = gi_n0;
#pragma unroll
            for (int e = 0; e < Ez; ++e) {
                float w_r = wih_s[e * 8 + jj * 4 + 0];
                float w_z = wih_s[e * 8 + jj * 4 + 1];
                float w_n = wih_s[e * 8 + jj * 4 + 2];
                float e0 = emb_s[xv0 * 17 + e];
                float e1 = emb_s[xv1 * 17 + e];
                gi_r0 += e0 * w_r; gi_z0 += e0 * w_z; gi_n0 += e0 * w_n;
                gi_r1 += e1 * w_r; gi_z1 += e1 * w_z; gi_n1 += e1 * w_n;
            }
        }

        // K half-loop: gh partials for (2 batches) x (1 j) x (3 gates)
        float ar0 = 0.f, az0 = 0.f, an0 = 0.f;
        float ar1 = 0.f, az1 = 0.f, an1 = 0.f;
        const float* hp = hrow + kofs * Bz + 2 * bb;
        const float* wp = w_s + kofs * 8 + jj * 4;
#pragma unroll 32
        for (int k = 0; k < 128; ++k) {
            float2 h2 = *(const float2*)(hp + k * Bz);
            float4 w  = *(const float4*)(wp + k * 8);
            ar0 += h2.x * w.x; az0 += h2.x * w.y; an0 += h2.x * w.z;
            ar1 += h2.y * w.x; az1 += h2.y * w.y; an1 += h2.y * w.z;
        }

        if (half) {
            float* r = &red_s[lt * 12];
            r[0] = ar0;   r[1] = az0;   r[2] = an0;
            r[3] = ar1;   r[4] = az1;   r[5] = an1;
            r[6] = gi_r0; r[7] = gi_z0; r[8] = gi_n0;
            r[9] = gi_r1; r[10] = gi_z1; r[11] = gi_n1;
        }
        __syncthreads();

        if (!half) {
            const float* r = &red_s[lt * 12];
            float sr0 = ar0 + r[0], sz0 = az0 + r[1], sn0 = an0 + r[2];
            float sr1 = ar1 + r[3], sz1 = az1 + r[4], sn1 = an1 + r[5];
            float bhr = bias_s[8 + jj * 4 + 0];
            float bhz = bias_s[8 + jj * 4 + 1];
            float bhn = bias_s[8 + jj * 4 + 2];
            float hp0 = hrow[j * Bz + 2 * bb];
            float hp1 = hrow[j * Bz + 2 * bb + 1];

            float rr0 = sigmf(r[6] + sr0 + bhr);
            float zz0 = sigmf(r[7] + sz0 + bhz);
            float nn0 = tanhf(r[8] + rr0 * (sn0 + bhn));
            float hn0 = (1.0f - zz0) * nn0 + zz0 * hp0;

            float rr1 = sigmf(r[9]  + sr1 + bhr);
            float zz1 = sigmf(r[10] + sz1 + bhz);
            float nn1 = tanhf(r[11] + rr1 * (sn1 + bhn));
            float hn1 = (1.0f - zz1) * nn1 + zz1 * hp1;

            *(float2*)&g_hseq[t + 1][j][2 * bb] = make_float2(hn0, hn1);
        }

        // ---- grid-wide barrier (all CTAs co-resident: grid 128 <= 148 SMs) ----
        __threadfence();          // release h writes at gpu scope
        __syncthreads();
        if (tid == 0) {
            atomicAdd(&g_bar, 1u);
            unsigned target = (unsigned)(t + 1) * (unsigned)NCTA;
            while (*(volatile unsigned*)&g_bar < target) { }
            __threadfence();      // acquire other CTAs' h writes
        }
        __syncthreads();
    }

    // reset counters so graph replays see a clean state; the last CTA to
    // arrive here resets (all others have already passed their final poll).
    if (tid == 0) {
        unsigned d = atomicAdd(&g_done, 1u);
        if (d == NCTA - 1u) { g_bar = 0u; g_done = 0u; }
    }
}

// ---------------------------------------------------------------------------
// Phase 2: out[b,t,:] = h_t[b,:] @ W_out + b_out.
// Grid (512 t, 2 b-halves); CTA computes a [64 b x 256 v] tile with h and a
// 64-wide W_out column chunk staged in smem; per-thread 4x4 register tile.
// ---------------------------------------------------------------------------
__global__ void __launch_bounds__(256, 1)
gru_phase2(const float* __restrict__ W_out, const float* __restrict__ b_out,
           float* __restrict__ out)
{
    extern __shared__ float sm2[];
    float* h_s = sm2;               // [256 j][64 b]   64 KB
    float* w_sO = sm2 + 256 * 64;   // [256 j][64 v]   64 KB

    const int tid = threadIdx.x;
    const int t   = blockIdx.x;     // 0..511
    const int bh  = blockIdx.y;     // 0..1

    const float* hsrc = &g_hseq[t + 1][0][bh * 64];
    for (int i = tid; i < 256 * 16; i += 256) {
        int jrow = i >> 4, col4 = i & 15;
        ((float4*)h_s)[i] = *(const float4*)(hsrc + jrow * 128 + col4 * 4);
    }

    const int bi = tid & 15;        // b-local tile: 4*bi .. 4*bi+3
    const int vi = tid >> 4;        // v-in-chunk tile: 4*vi .. 4*vi+3

    for (int ch = 0; ch < 4; ++ch) {
        __syncthreads();            // w_s reuse / h_s ready
        for (int i = tid; i < 256 * 16; i += 256) {
            int jrow = i >> 4, col4 = i & 15;
            ((float4*)w_sO)[i] = *(const float4*)(W_out + jrow * 256 + ch * 64 + col4 * 4);
        }
        __syncthreads();

        float a00=0,a01=0,a02=0,a03=0, a10=0,a11=0,a12=0,a13=0;
        float a20=0,a21=0,a22=0,a23=0, a30=0,a31=0,a32=0,a33=0;
#pragma unroll 16
        for (int jrow = 0; jrow < 256; ++jrow) {
            float4 hv = *(const float4*)&h_s[jrow * 64 + 4 * bi];
            float4 wv = *(const float4*)&w_sO[jrow * 64 + 4 * vi];
            a00 += hv.x * wv.x; a01 += hv.x * wv.y; a02 += hv.x * wv.z; a03 += hv.x * wv.w;
            a10 += hv.y * wv.x; a11 += hv.y * wv.y; a12 += hv.y * wv.z; a13 += hv.y * wv.w;
            a20 += hv.z * wv.x; a21 += hv.z * wv.y; a22 += hv.z * wv.z; a23 += hv.z * wv.w;
            a30 += hv.w * wv.x; a31 += hv.w * wv.y; a32 += hv.w * wv.z; a33 += hv.w * wv.w;
        }

        float4 bo = *(const float4*)(b_out + ch * 64 + 4 * vi);
        const int vbase = ch * 64 + 4 * vi;
        {
            int b = bh * 64 + 4 * bi;
            float4 o;
            o.x=a00+bo.x; o.y=a01+bo.y; o.z=a02+bo.z; o.w=a03+bo.w;
            *(float4*)&out[(size_t)(b+0) * (Sz*Vz) + (size_t)t * Vz + vbase] = o;
            o.x=a10+bo.x; o.y=a11+bo.y; o.z=a12+bo.z; o.w=a13+bo.w;
            *(float4*)&out[(size_t)(b+1) * (Sz*Vz) + (size_t)t * Vz + vbase] = o;
            o.x=a20+bo.x; o.y=a21+bo.y; o.z=a22+bo.z; o.w=a23+bo.w;
            *(float4*)&out[(size_t)(b+2) * (Sz*Vz) + (size_t)t * Vz + vbase] = o;
            o.x=a30+bo.x; o.y=a31+bo.y; o.z=a32+bo.z; o.w=a33+bo.w;
            *(float4*)&out[(size_t)(b+3) * (Sz*Vz) + (size_t)t * Vz + vbase] = o;
        }
    }
}

extern "C" void kernel_launch(void* const* d_in, const int* in_sizes, int n_in,
                              void* d_out, int out_size)
{
    const int*   x     = (const int*)  d_in[0];
    const float* embed = (const float*)d_in[1];
    const float* W_ih  = (const float*)d_in[2];
    const float* b_ih  = (const float*)d_in[3];
    const float* W_hh  = (const float*)d_in[4];
    const float* b_hh  = (const float*)d_in[5];
    const float* W_out = (const float*)d_in[6];
    const float* b_out = (const float*)d_in[7];
    float* out = (float*)d_out;

    cudaFuncSetAttribute(gru_phase2, cudaFuncAttributeMaxDynamicSharedMemorySize, 131072);

    gru_phase1<<<NCTA, 256>>>(x, embed, W_ih, b_ih, W_hh, b_hh);
    gru_phase2<<<dim3(Sz, 2), 256, 131072>>>(W_out, b_out, out);
}

// round 3
// speedup vs baseline: 1.0184x; 1.0184x over previous
#include <cuda_runtime.h>

#define Bz 128
#define Sz 512
#define Hz 256
#define Vz 256
#define NCTA 128

typedef unsigned long long ull;

// h sequence, slab 0 = h0 = zeros (never written). Layout [t][b][j].
__device__ float g_hseq[Sz + 1][Bz][Hz];   // ~67 MB, zero-init at module load
__device__ unsigned g_bar = 0;             // monotonic grid barrier counter
__device__ unsigned g_done = 0;            // end-of-kernel reset rendezvous

__device__ __forceinline__ void fma2(ull& acc, ull a, ull b) {
    asm("fma.rn.f32x2 %0, %1, %2, %3;" : "=l"(acc) : "l"(a), "l"(b), "l"(acc));
}
__device__ __forceinline__ float f2sum(ull v) {
    return __uint_as_float((unsigned)v) + __uint_as_float((unsigned)(v >> 32));
}
__device__ __forceinline__ ull fdup(float v) {
    ull r; unsigned u = __float_as_uint(v);
    asm("mov.b64 %0, {%1, %1};" : "=l"(r) : "r"(u));
    return r;
}
__device__ __forceinline__ float sigmf(float v) { return 1.0f / (1.0f + __expf(-v)); }

// ---- phase-1 dynamic smem layout (offsets in floats) ----
// FIXED from R2: OFF_RED is 8*8*32 float4 = 8192 floats (32 KB), not 4096.
#define OFF_WRZ 0        // float4[128 kp][32 j] = (r_k, r_k1, z_k, z_k1)      64 KB
#define OFF_WN  16384    // float2[128 kp][32 j] = (n_k, n_k1)                 32 KB
#define OFF_H   24576    // float [8 b][256 k]                                  8 KB
#define OFF_RED 26624    // float4[8 kc][8 b][32 j]                            32 KB
#define OFF_GI  34816    // float4[8 b][32 j]                                   4 KB
#define OFF_WIH 35840    // float4[16 e][32 j]                                  8 KB
#define OFF_BIH 37888    // float4[32 j]
#define OFF_BHH 38016    // float4[32 j]
#define OFF_EMB 38144    // float [256 v][17]                                  17 KB
#define OFF_X   42496    // int   [8 b][512 s]                                 16 KB
#define SM1_FLOATS 46592 // 186368 bytes

__device__ __forceinline__ void compute_gi(float* sm, int tid, int t) {
    int b = tid >> 5, j2 = tid & 31;
    const int* xs = (const int*)(sm + OFF_X);
    int xv = xs[b * Sz + t];
    float4 acc = ((const float4*)(sm + OFF_BIH))[j2];
    const float* emb = sm + OFF_EMB;
    const float4* wih = (const float4*)(sm + OFF_WIH);
#pragma unroll
    for (int e = 0; e < 16; ++e) {
        float ev = emb[xv * 17 + e];
        float4 wv = wih[e * 32 + j2];
        acc.x += ev * wv.x; acc.y += ev * wv.y; acc.z += ev * wv.z;
    }
    ((float4*)(sm + OFF_GI))[b * 32 + j2] = acc;
}

// ---------------------------------------------------------------------------
// Phase 1: persistent GRU recurrence. 128 CTAs = 16 b-tiles(8) x 8 j-tiles(32).
// 8 warps = 8 k-chunks of 32 k (16 k-pairs); lane = j; reg-tile = 8 b x 3 gates
// as f32x2 over k-pairs (FFMA2). Grid barrier each step; gi overlapped into
// the barrier wait.
// ---------------------------------------------------------------------------
__global__ void __launch_bounds__(256, 1)
gru_phase1(const int* __restrict__ x,
           const float* __restrict__ embed,
           const float* __restrict__ W_ih, const float* __restrict__ b_ih,
           const float* __restrict__ W_hh, const float* __restrict__ b_hh)
{
    extern __shared__ float sm[];
    const int tid = threadIdx.x;
    const int jt = blockIdx.x & 7, bt = blockIdx.x >> 3;
    const int j0 = jt * 32, b0 = bt * 8;

    // ---- one-time fills ----
    float4* wrz4 = (float4*)(sm + OFF_WRZ);
    float2* wn2  = (float2*)(sm + OFF_WN);
    for (int i = tid; i < 128 * 32; i += 256) {
        int kp = i >> 5, j2 = i & 31, jg = j0 + j2;
        const float* wr0 = W_hh + (2 * kp) * 768 + jg;
        const float* wr1 = W_hh + (2 * kp + 1) * 768 + jg;
        wrz4[i] = make_float4(wr0[0], wr1[0], wr0[256], wr1[256]);
        wn2[i]  = make_float2(wr0[512], wr1[512]);
    }
    for (int i = tid; i < Vz * 16; i += 256) {
        int v = i >> 4, e = i & 15;
        sm[OFF_EMB + v * 17 + e] = embed[i];
    }
    {
        float4* wih4 = (float4*)(sm + OFF_WIH);
        for (int i = tid; i < 16 * 32; i += 256) {
            int e = i >> 5, j2 = i & 31, jg = j0 + j2;
            wih4[i] = make_float4(W_ih[e * 768 + jg], W_ih[e * 768 + 256 + jg],
                                  W_ih[e * 768 + 512 + jg], 0.f);
        }
    }
    if (tid < 32) {
        ((float4*)(sm + OFF_BIH))[tid] =
            make_float4(b_ih[j0 + tid], b_ih[256 + j0 + tid], b_ih[512 + j0 + tid], 0.f);
        ((float4*)(sm + OFF_BHH))[tid] =
            make_float4(b_hh[j0 + tid], b_hh[256 + j0 + tid], b_hh[512 + j0 + tid], 0.f);
    }
    {
        int4* xs4 = (int4*)(sm + OFF_X);
        const int4* xg = (const int4*)x;
        for (int i = tid; i < 1024; i += 256) {
            int bb = i >> 7, s4 = i & 127;
            xs4[i] = xg[(b0 + bb) * 128 + s4];
        }
    }
    __syncthreads();
    compute_gi(sm, tid, 0);

    const int w  = tid >> 5;
    const int jl = tid & 31;
    float*  hs   = sm + OFF_H;
    float4* red4 = (float4*)(sm + OFF_RED);

    for (int t = 0; t < Sz; ++t) {
        // ---- stage h tile: 8 rows x 256, coalesced ----
        {
            const float* hsrc = &g_hseq[t][b0 + w][0];
            float4 A = *(const float4*)&hsrc[jl * 4];
            float4 B = *(const float4*)&hsrc[128 + jl * 4];
            *(float4*)&hs[w * 256 + jl * 4]       = A;
            *(float4*)&hs[w * 256 + 128 + jl * 4] = B;
        }
        __syncthreads();   // h_s + gi_s ready

        // ---- k-chunk loop: FFMA2 over k-pairs ----
        ull ar[8], az[8], an[8];
#pragma unroll
        for (int b = 0; b < 8; ++b) { ar[b] = 0ull; az[b] = 0ull; an[b] = 0ull; }
        const int kp0 = w * 16;
#pragma unroll
        for (int q = 0; q < 8; ++q) {            // k-quads (4 k = 2 kpairs)
            const int kb = kp0 * 2 + q * 4;
            ulonglong2 h01[8];
#pragma unroll
            for (int b = 0; b < 8; ++b)
                h01[b] = *(const ulonglong2*)&hs[b * 256 + kb];
#pragma unroll
            for (int p = 0; p < 2; ++p) {
                const int kp = kp0 + q * 2 + p;
                ulonglong2 wrz = *(const ulonglong2*)&wrz4[kp * 32 + jl];
                ull        wn  = *(const ull*)&wn2[kp * 32 + jl];
#pragma unroll
                for (int b = 0; b < 8; ++b) {
                    ull h = p ? h01[b].y : h01[b].x;
                    fma2(ar[b], h, wrz.x);
                    fma2(az[b], h, wrz.y);
                    fma2(an[b], h, wn);
                }
            }
        }
#pragma unroll
        for (int b = 0; b < 8; ++b)
            red4[(w * 8 + b) * 32 + jl] =
                make_float4(f2sum(ar[b]), f2sum(az[b]), f2sum(an[b]), 0.f);
        __syncthreads();

        // ---- finalize gates: one (b, j) pair per thread ----
        {
            int b = tid >> 5, j2 = tid & 31;
            float sr = 0.f, szz = 0.f, sn = 0.f;
#pragma unroll
            for (int kc = 0; kc < 8; ++kc) {
                float4 p = red4[(kc * 8 + b) * 32 + j2];
                sr += p.x; szz += p.y; sn += p.z;
            }
            float4 gi = ((const float4*)(sm + OFF_GI))[b * 32 + j2];
            float4 bh = ((const float4*)(sm + OFF_BHH))[j2];
            float hprev = hs[b * 256 + j0 + j2];
            float r = sigmf(gi.x + sr + bh.x);
            float z = sigmf(gi.y + szz + bh.y);
            float n = tanhf(gi.z + r * (sn + bh.z));
            g_hseq[t + 1][b0 + b][j0 + j2] = (1.0f - z) * n + z * hprev;
        }

        if (t + 1 < Sz) {
            __threadfence();          // release h writes at gpu scope
            __syncthreads();
            if (tid == 0) atomicAdd(&g_bar, 1u);
            compute_gi(sm, tid, t + 1);   // overlap with barrier wait
            if (tid == 0) {
                unsigned target = (unsigned)(t + 1) * (unsigned)NCTA;
                while (*(volatile unsigned*)&g_bar < target) { }
                __threadfence();      // acquire other CTAs' h writes
            }
            __syncthreads();
        }
    }

    // reset counters so graph replays see a clean state
    if (tid == 0) {
        unsigned d = atomicAdd(&g_done, 1u);
        if (d == NCTA - 1u) { g_bar = 0u; g_done = 0u; }
    }
}

// ---------------------------------------------------------------------------
// Phase 2: out[b,t,:] = h_t[b,:] @ W_out + b_out, FFMA2 paired over v.
// Grid (512 t, 4 b-quarters); CTA tile = 32 b x 256 v in 4 chunks of 64 v.
// Thread = (8 v, 1 b): w-pairs come contiguous from W_out rows (no interleave).
// ---------------------------------------------------------------------------
__global__ void __launch_bounds__(256, 2)
gru_phase2(const float* __restrict__ W_out, const float* __restrict__ b_out,
           float* __restrict__ out)
{
    extern __shared__ float sm2[];
    float* hs = sm2;                 // [32 b][260]  (pad 4)
    float* ws = sm2 + 32 * 260;      // [256 k][68]  (pad 4)

    const int tid = threadIdx.x;
    const int t  = blockIdx.x;
    const int b0 = blockIdx.y * 32;

    // stage h: 32 rows x 256, coalesced
    for (int r = 0; r < 8; ++r) {
        int idx = tid + 256 * r;          // float4 slots over [32][64]
        int bb = idx >> 6, c4 = idx & 63;
        *(float4*)&hs[bb * 260 + c4 * 4] =
            *(const float4*)&g_hseq[t + 1][b0 + bb][c4 * 4];
    }

    const int v8 = tid & 7;     // v = v8*8 .. +7 within chunk
    const int bb = tid >> 3;    // 0..31
    const float* hrow = &hs[bb * 260];

    for (int ch = 0; ch < 4; ++ch) {
        __syncthreads();        // prev compute done / h staged
        for (int r = 0; r < 16; ++r) {
            int idx = tid + 256 * r;      // float4 slots over [256][16]
            int k = idx >> 4, c4 = idx & 15;
            *(float4*)&ws[k * 68 + c4 * 4] =
                *(const float4*)&W_out[k * 256 + ch * 64 + c4 * 4];
        }
        __syncthreads();

        ull a0 = 0ull, a1 = 0ull, a2 = 0ull, a3 = 0ull;
        const float* wp = &ws[v8 * 8];
#pragma unroll 8
        for (int k = 0; k < 256; ++k) {
            ull h2 = fdup(hrow[k]);
            ulonglong2 wA = *(const ulonglong2*)&wp[k * 68];
            ulonglong2 wB = *(const ulonglong2*)&wp[k * 68 + 4];
            fma2(a0, h2, wA.x); fma2(a1, h2, wA.y);
            fma2(a2, h2, wB.x); fma2(a3, h2, wB.y);
        }

        int vb = ch * 64 + v8 * 8;
        float4 bo0 = *(const float4*)&b_out[vb];
        float4 bo1 = *(const float4*)&b_out[vb + 4];
        float4 o0, o1;
        o0.x = __uint_as_float((unsigned)a0)         + bo0.x;
        o0.y = __uint_as_float((unsigned)(a0 >> 32)) + bo0.y;
        o0.z = __uint_as_float((unsigned)a1)         + bo0.z;
        o0.w = __uint_as_float((unsigned)(a1 >> 32)) + bo0.w;
        o1.x = __uint_as_float((unsigned)a2)         + bo1.x;
        o1.y = __uint_as_float((unsigned)(a2 >> 32)) + bo1.y;
        o1.z = __uint_as_float((unsigned)a3)         + bo1.z;
        o1.w = __uint_as_float((unsigned)(a3 >> 32)) + bo1.w;
        size_t obase = (size_t)(b0 + bb) * (Sz * Vz) + (size_t)t * Vz + vb;
        *(float4*)&out[obase]     = o0;
        *(float4*)&out[obase + 4] = o1;
    }
}

extern "C" void kernel_launch(void* const* d_in, const int* in_sizes, int n_in,
                              void* d_out, int out_size)
{
    const int*   x     = (const int*)  d_in[0];
    const float* embed = (const float*)d_in[1];
    const float* W_ih  = (const float*)d_in[2];
    const float* b_ih  = (const float*)d_in[3];
    const float* W_hh  = (const float*)d_in[4];
    const float* b_hh  = (const float*)d_in[5];
    const float* W_out = (const float*)d_in[6];
    const float* b_out = (const float*)d_in[7];
    float* out = (float*)d_out;

    cudaFuncSetAttribute(gru_phase1, cudaFuncAttributeMaxDynamicSharedMemorySize,
                         SM1_FLOATS * 4);
    cudaFuncSetAttribute(gru_phase2, cudaFuncAttributeMaxDynamicSharedMemorySize,
                         (32 * 260 + 256 * 68) * 4);

    gru_phase1<<<NCTA, 256, SM1_FLOATS * 4>>>(x, embed, W_ih, b_ih, W_hh, b_hh);
    gru_phase2<<<dim3(Sz, 4), 256, (32 * 260 + 256 * 68) * 4>>>(W_out, b_out, out);
}